// round 14
// baseline (speedup 1.0000x reference)
#include <cuda_runtime.h>
#include <cuda_fp16.h>
#include <cstdint>

#define N_NODES 50000
#define N_EDGES 800000
#define C 32
#define BN_EPS 1e-5f

// ---------------- device scratch ----------------
__device__ __align__(16) __half g_Ah[N_NODES * C];          // x@W1_top + b1 (fp16)
__device__ __align__(16) __half g_Bh[N_NODES * C];          // x@W1_bot (fp16)
__device__ __align__(16) __half g_y1h[(size_t)N_EDGES * C]; // 51.2 MB raw y1 (fp16)
__device__ __align__(16) __half g_y2h[(size_t)N_EDGES * C]; // 51.2 MB y2 (fp16)
__device__ float g_stat1[64];
__device__ float g_stat2[64];

__device__ __forceinline__ void red_add_v4(float* p, float a, float b, float c, float d) {
    asm volatile("red.global.add.v4.f32 [%0], {%1, %2, %3, %4};"
                 :: "l"(p), "f"(a), "f"(b), "f"(c), "f"(d) : "memory");
}
__device__ __forceinline__ unsigned h2_bits(__half2 h) { return *(unsigned*)&h; }

// ---------------- K1: zero out + stats + per-node precompute ---------------
__global__ void k1_node(const float* __restrict__ x, const float* __restrict__ W1,
                        const float* __restrict__ b1, float* __restrict__ out) {
    int g = blockIdx.x * blockDim.x + threadIdx.x;
    if (g < N_NODES * C) out[g] = 0.f;   // grid = 6250*256 = 1.6M = N_NODES*C
    if (g < 64) { g_stat1[g] = 0.f; g_stat2[g] = 0.f; }

    __shared__ float sW[2 * C * C];
    for (int i = threadIdx.x; i < 2 * C * C; i += blockDim.x) sW[i] = W1[i];
    __syncthreads();
    int warp = threadIdx.x >> 5, lane = threadIdx.x & 31;
    int node = blockIdx.x * (blockDim.x >> 5) + warp;
    if (node >= N_NODES) return;
    float xv = x[node * C + lane];
    float a = b1[lane], b = 0.f;
#pragma unroll
    for (int i = 0; i < C; i++) {
        float xi = __shfl_sync(0xffffffffu, xv, i);
        a = fmaf(xi, sW[i * C + lane], a);
        b = fmaf(xi, sW[(i + C) * C + lane], b);
    }
    g_Ah[node * C + lane] = __float2half(a);
    g_Bh[node * C + lane] = __float2half(b);
}

// ------- K2: gather once -> stats1 + materialize y1 (fp16, sequential) -----
__global__ void __launch_bounds__(256) k2_stats1(const int* __restrict__ ei) {
    int g = blockIdx.x * blockDim.x + threadIdx.x;
    int nthr = gridDim.x * blockDim.x;
    int chunk = g & 7; // 4 channels [chunk*4, chunk*4+4)
    float s[4], q[4];
#pragma unroll
    for (int i = 0; i < 4; i++) { s[i] = 0.f; q[i] = 0.f; }
    const uint2* A2 = (const uint2*)g_Ah;
    const uint2* B2 = (const uint2*)g_Bh;
    const int HALF = N_EDGES / 2;
    for (int e = g >> 3; e < HALF; e += nthr >> 3) {
        int e2 = e + HALF;
        int rowA = ei[e],  colA = ei[N_EDGES + e];
        int rowB = ei[e2], colB = ei[N_EDGES + e2];
        uint2 avA = A2[rowA * 8 + chunk];
        uint2 bvA = B2[colA * 8 + chunk];
        uint2 avB = A2[rowB * 8 + chunk];
        uint2 bvB = B2[colB * 8 + chunk];
        float2 a0, a1, b0, b1;
        float y0, y1, y2, y3;

        a0 = __half22float2(*(const __half2*)&avA.x);
        a1 = __half22float2(*(const __half2*)&avA.y);
        b0 = __half22float2(*(const __half2*)&bvA.x);
        b1 = __half22float2(*(const __half2*)&bvA.y);
        y0 = a0.x + b0.x; y1 = a0.y + b0.y; y2 = a1.x + b1.x; y3 = a1.y + b1.y;
        s[0] += y0; q[0] = fmaf(y0, y0, q[0]);
        s[1] += y1; q[1] = fmaf(y1, y1, q[1]);
        s[2] += y2; q[2] = fmaf(y2, y2, q[2]);
        s[3] += y3; q[3] = fmaf(y3, y3, q[3]);
        {
            __half2 p01 = __floats2half2_rn(y0, y1);
            __half2 p23 = __floats2half2_rn(y2, y3);
            *(uint2*)(g_y1h + (size_t)e * C + chunk * 4) =
                make_uint2(h2_bits(p01), h2_bits(p23));
        }

        a0 = __half22float2(*(const __half2*)&avB.x);
        a1 = __half22float2(*(const __half2*)&avB.y);
        b0 = __half22float2(*(const __half2*)&bvB.x);
        b1 = __half22float2(*(const __half2*)&bvB.y);
        y0 = a0.x + b0.x; y1 = a0.y + b0.y; y2 = a1.x + b1.x; y3 = a1.y + b1.y;
        s[0] += y0; q[0] = fmaf(y0, y0, q[0]);
        s[1] += y1; q[1] = fmaf(y1, y1, q[1]);
        s[2] += y2; q[2] = fmaf(y2, y2, q[2]);
        s[3] += y3; q[3] = fmaf(y3, y3, q[3]);
        {
            __half2 p01 = __floats2half2_rn(y0, y1);
            __half2 p23 = __floats2half2_rn(y2, y3);
            *(uint2*)(g_y1h + (size_t)e2 * C + chunk * 4) =
                make_uint2(h2_bits(p01), h2_bits(p23));
        }
    }
#pragma unroll
    for (int off = 8; off < 32; off <<= 1) {
#pragma unroll
        for (int i = 0; i < 4; i++) {
            s[i] += __shfl_xor_sync(0xffffffffu, s[i], off);
            q[i] += __shfl_xor_sync(0xffffffffu, q[i], off);
        }
    }
    __shared__ float sh[64];
    if (threadIdx.x < 64) sh[threadIdx.x] = 0.f;
    __syncthreads();
    int lane = threadIdx.x & 31;
    if (lane < 8) {
#pragma unroll
        for (int i = 0; i < 4; i++) {
            atomicAdd(&sh[chunk * 4 + i], s[i]);
            atomicAdd(&sh[32 + chunk * 4 + i], q[i]);
        }
    }
    __syncthreads();
    if (threadIdx.x < 64) atomicAdd(&g_stat1[threadIdx.x], sh[threadIdx.x]);
}

// ------- K4: sequential y1 read -> BN1+ReLU -> mt-tiled tensor GEMM --------
#define HT 40  // fp16 h-tile stride (halves)
__global__ void __launch_bounds__(128, 6) k4_main(const float* __restrict__ W2,
                                                  const float* __restrict__ b2,
                                                  const float* __restrict__ gamma1,
                                                  const float* __restrict__ beta1) {
    __shared__ __half sh_h[256 * HT];   // 20.5 KB
    __shared__ __half sWT[C * C];       // W2^T fp16 [n][k]
    __shared__ float sS1[C], sT1[C];
    __shared__ float sStat[4 * 64];
    int tid = threadIdx.x;

    for (int i = tid; i < C * C; i += 128) {
        int k = i >> 5, n = i & 31;
        sWT[n * C + k] = __float2half(W2[i]);
    }
    if (tid < C) {
        const float invE = 1.f / (float)N_EDGES;
        float mean = g_stat1[tid] * invE;
        float var = g_stat1[32 + tid] * invE - mean * mean;
        float s = gamma1[tid] * rsqrtf(var + BN_EPS);
        sS1[tid] = s;
        sT1[tid] = beta1[tid] - mean * s;
    }
    __syncthreads();

    // ---- phase 1: coalesced sequential y1 read + BN1 + ReLU -> fp16 tile --
    int q = tid & 7;
    float s1v[4], t1v[4];
#pragma unroll
    for (int j = 0; j < 4; j++) { s1v[j] = sS1[q * 4 + j]; t1v[j] = sT1[q * 4 + j]; }
#pragma unroll
    for (int r = 0; r < 16; r++) {
        int el = (tid >> 3) + r * 16;
        size_t e = (size_t)blockIdx.x * 256 + el;
        uint2 v = *(const uint2*)(g_y1h + e * C + q * 4);
        float2 f0 = __half22float2(*(const __half2*)&v.x);
        float2 f1 = __half22float2(*(const __half2*)&v.y);
        float h0 = fmaxf(fmaf(f0.x, s1v[0], t1v[0]), 0.f);
        float h1 = fmaxf(fmaf(f0.y, s1v[1], t1v[1]), 0.f);
        float h2 = fmaxf(fmaf(f1.x, s1v[2], t1v[2]), 0.f);
        float h3 = fmaxf(fmaf(f1.y, s1v[3], t1v[3]), 0.f);
        __half2 p01 = __floats2half2_rn(h0, h1);
        __half2 p23 = __floats2half2_rn(h2, h3);
        *(uint2*)(&sh_h[el * HT + q * 4]) = make_uint2(h2_bits(p01), h2_bits(p23));
    }
    __syncthreads();

    // ---- phase 2: mt-tiled GEMM (short-lived accumulators) ----
    int w = tid >> 5, l = tid & 31;
    int lq = l & 3, lr = l >> 2;

    unsigned bfr[4][2][2];
#pragma unroll
    for (int nt = 0; nt < 4; nt++)
#pragma unroll
        for (int kk = 0; kk < 2; kk++) {
            const __half* base = sWT + (lr + 8 * nt) * C + 2 * lq + 16 * kk;
            bfr[nt][kk][0] = *(const unsigned*)(base);
            bfr[nt][kk][1] = *(const unsigned*)(base + 8);
        }
    float bx[4], by[4];
#pragma unroll
    for (int nt = 0; nt < 4; nt++) {
        bx[nt] = b2[2 * lq + 8 * nt];
        by[nt] = b2[2 * lq + 8 * nt + 1];
    }
    float sv[4][2], qv[4][2];
#pragma unroll
    for (int nt = 0; nt < 4; nt++) { sv[nt][0] = sv[nt][1] = qv[nt][0] = qv[nt][1] = 0.f; }

    size_t ebase = (size_t)blockIdx.x * 256 + w * 64;
#pragma unroll
    for (int mt = 0; mt < 4; mt++) {
        float d[4][4];
#pragma unroll
        for (int nt = 0; nt < 4; nt++) {
            d[nt][0] = bx[nt]; d[nt][1] = by[nt];
            d[nt][2] = bx[nt]; d[nt][3] = by[nt];
        }
        int r0 = w * 64 + mt * 16 + lr;
#pragma unroll
        for (int kk = 0; kk < 2; kk++) {
            unsigned a0 = *(const unsigned*)(&sh_h[r0 * HT + 2 * lq + 16 * kk]);
            unsigned a1 = *(const unsigned*)(&sh_h[(r0 + 8) * HT + 2 * lq + 16 * kk]);
            unsigned a2 = *(const unsigned*)(&sh_h[r0 * HT + 2 * lq + 8 + 16 * kk]);
            unsigned a3 = *(const unsigned*)(&sh_h[(r0 + 8) * HT + 2 * lq + 8 + 16 * kk]);
#pragma unroll
            for (int nt = 0; nt < 4; nt++) {
                asm volatile(
                    "mma.sync.aligned.m16n8k16.row.col.f32.f16.f16.f32 "
                    "{%0,%1,%2,%3}, {%4,%5,%6,%7}, {%8,%9}, {%0,%1,%2,%3};"
                    : "+f"(d[nt][0]), "+f"(d[nt][1]), "+f"(d[nt][2]), "+f"(d[nt][3])
                    : "r"(a0), "r"(a1), "r"(a2), "r"(a3),
                      "r"(bfr[nt][kk][0]), "r"(bfr[nt][kk][1]));
            }
        }
        // store this mt-tile + stats
        size_t row0 = ebase + mt * 16 + lr;
        size_t row1 = row0 + 8;
#pragma unroll
        for (int nt = 0; nt < 4; nt++) {
            float d0 = d[nt][0], d1 = d[nt][1], d2 = d[nt][2], d3 = d[nt][3];
            __half2 ph0 = __floats2half2_rn(d0, d1);
            __half2 ph1 = __floats2half2_rn(d2, d3);
            int cw = 2 * lq + 8 * nt;
            *(unsigned*)(g_y2h + row0 * C + cw) = h2_bits(ph0);
            *(unsigned*)(g_y2h + row1 * C + cw) = h2_bits(ph1);
            sv[nt][0] += d0 + d2;  qv[nt][0] += d0 * d0 + d2 * d2;
            sv[nt][1] += d1 + d3;  qv[nt][1] += d1 * d1 + d3 * d3;
        }
    }

    // ---- stats2 block reduce ----
#pragma unroll
    for (int off = 4; off < 32; off <<= 1) {
#pragma unroll
        for (int nt = 0; nt < 4; nt++)
#pragma unroll
            for (int j = 0; j < 2; j++) {
                sv[nt][j] += __shfl_xor_sync(0xffffffffu, sv[nt][j], off);
                qv[nt][j] += __shfl_xor_sync(0xffffffffu, qv[nt][j], off);
            }
    }
    if (lr == 0) {
#pragma unroll
        for (int nt = 0; nt < 4; nt++)
#pragma unroll
            for (int j = 0; j < 2; j++) {
                int c = 2 * lq + 8 * nt + j;
                sStat[w * 64 + c] = sv[nt][j];
                sStat[w * 64 + 32 + c] = qv[nt][j];
            }
    }
    __syncthreads();
    if (tid < 64)
        atomicAdd(&g_stat2[tid],
                  sStat[tid] + sStat[64 + tid] + sStat[128 + tid] + sStat[192 + tid]);
}

// ---------------- K7: BN2+ReLU + vector atomic scatter ---------------------
__global__ void __launch_bounds__(256) k7_scatter(const int* __restrict__ ei,
                                                  const float* __restrict__ gamma2,
                                                  const float* __restrict__ beta2,
                                                  float* __restrict__ out) {
    __shared__ float sS2[C], sT2[C];
    if (threadIdx.x < C) {
        int c = threadIdx.x;
        const float invE = 1.f / (float)N_EDGES;
        float mean = g_stat2[c] * invE;
        float var = g_stat2[32 + c] * invE - mean * mean;
        float s = gamma2[c] * rsqrtf(var + BN_EPS);
        sS2[c] = s;
        sT2[c] = beta2[c] - mean * s;
    }
    __syncthreads();
    int g = blockIdx.x * blockDim.x + threadIdx.x; // grid = E*4/256
    int e = g >> 2;
    int chunk = g & 3; // 8 channels
    int row = ei[e];
    const uint4* Y = (const uint4*)g_y2h;
    uint4 v = Y[(size_t)e * 4 + chunk];
    const unsigned* w = (const unsigned*)&v;
    float h[8];
#pragma unroll
    for (int p = 0; p < 4; p++) {
        float2 f = __half22float2(*(const __half2*)&w[p]);
        int c = chunk * 8 + 2 * p;
        h[2 * p]     = fmaxf(fmaf(f.x, sS2[c],     sT2[c]),     0.f);
        h[2 * p + 1] = fmaxf(fmaf(f.y, sS2[c + 1], sT2[c + 1]), 0.f);
    }
    float* dst = out + row * C + chunk * 8;
    red_add_v4(dst,     h[0], h[1], h[2], h[3]);
    red_add_v4(dst + 4, h[4], h[5], h[6], h[7]);
}

// ---------------- launch ----------------------------------------------------
extern "C" void kernel_launch(void* const* d_in, const int* in_sizes, int n_in,
                              void* d_out, int out_size) {
    const float* x      = (const float*)d_in[0];
    const float* W1     = (const float*)d_in[1];
    const float* b1     = (const float*)d_in[2];
    const float* gamma1 = (const float*)d_in[3];
    const float* beta1  = (const float*)d_in[4];
    const float* W2     = (const float*)d_in[5];
    const float* b2     = (const float*)d_in[6];
    const float* gamma2 = (const float*)d_in[7];
    const float* beta2  = (const float*)d_in[8];
    const int* ei       = (const int*)d_in[9];
    float* out = (float*)d_out;

    k1_node<<<N_NODES / 8, 256>>>(x, W1, b1, out);
    k2_stats1<<<2048, 256>>>(ei);
    k4_main<<<N_EDGES / 256, 128>>>(W2, b2, gamma1, beta1);
    k7_scatter<<<N_EDGES * 4 / 256, 256>>>(ei, gamma2, beta2, out);
}

// round 15
// speedup vs baseline: 1.0375x; 1.0375x over previous
#include <cuda_runtime.h>
#include <cuda_fp16.h>
#include <cstdint>

#define N_NODES 50000
#define N_EDGES 800000
#define C 32
#define BN_EPS 1e-5f

// ---------------- device scratch ----------------
__device__ __align__(16) __half g_Ah[N_NODES * C];          // x@W1_top + b1 (fp16)
__device__ __align__(16) __half g_Bh[N_NODES * C];          // x@W1_bot (fp16)
__device__ __align__(16) __half g_y2h[(size_t)N_EDGES * C]; // 51.2 MB fp16, edge order
__device__ float g_stat1[64];
__device__ float g_stat2[64];

__device__ __forceinline__ void red_add_v4(float* p, float a, float b, float c, float d) {
    asm volatile("red.global.add.v4.f32 [%0], {%1, %2, %3, %4};"
                 :: "l"(p), "f"(a), "f"(b), "f"(c), "f"(d) : "memory");
}
__device__ __forceinline__ unsigned h2_bits(__half2 h) { return *(unsigned*)&h; }

// ---------------- K1: zero out + stats + per-node precompute ---------------
__global__ void k1_node(const float* __restrict__ x, const float* __restrict__ W1,
                        const float* __restrict__ b1, float* __restrict__ out) {
    int g = blockIdx.x * blockDim.x + threadIdx.x;
    if (g < N_NODES * C) out[g] = 0.f;   // grid = 6250*256 = 1.6M = N_NODES*C
    if (g < 64) { g_stat1[g] = 0.f; g_stat2[g] = 0.f; }

    __shared__ float sW[2 * C * C];
    for (int i = threadIdx.x; i < 2 * C * C; i += blockDim.x) sW[i] = W1[i];
    __syncthreads();
    int warp = threadIdx.x >> 5, lane = threadIdx.x & 31;
    int node = blockIdx.x * (blockDim.x >> 5) + warp;
    if (node >= N_NODES) return;
    float xv = x[node * C + lane];
    float a = b1[lane], b = 0.f;
#pragma unroll
    for (int i = 0; i < C; i++) {
        float xi = __shfl_sync(0xffffffffu, xv, i);
        a = fmaf(xi, sW[i * C + lane], a);
        b = fmaf(xi, sW[(i + C) * C + lane], b);
    }
    g_Ah[node * C + lane] = __float2half(a);
    g_Bh[node * C + lane] = __float2half(b);
}

// ---------------- K2: stats1 of y1 = A[row]+B[col]; 4-way interleaved ------
__global__ void __launch_bounds__(256) k2_stats1(const int* __restrict__ ei) {
    int g = blockIdx.x * blockDim.x + threadIdx.x;
    int nthr = gridDim.x * blockDim.x;
    int chunk = g & 7; // 4 channels [chunk*4, chunk*4+4)
    float s[4], q[4];
#pragma unroll
    for (int i = 0; i < 4; i++) { s[i] = 0.f; q[i] = 0.f; }
    const uint2* A2 = (const uint2*)g_Ah;
    const uint2* B2 = (const uint2*)g_Bh;
    const int QTR = N_EDGES / 4;
    for (int e = g >> 3; e < QTR; e += nthr >> 3) {
        int e0 = e, e1 = e + QTR, e2 = e + 2 * QTR, e3 = e + 3 * QTR;
        int r0 = ei[e0], c0 = ei[N_EDGES + e0];
        int r1 = ei[e1], c1 = ei[N_EDGES + e1];
        int r2 = ei[e2], c2 = ei[N_EDGES + e2];
        int r3 = ei[e3], c3 = ei[N_EDGES + e3];
        uint2 av0 = A2[r0 * 8 + chunk], bv0 = B2[c0 * 8 + chunk];
        uint2 av1 = A2[r1 * 8 + chunk], bv1 = B2[c1 * 8 + chunk];
        uint2 av2 = A2[r2 * 8 + chunk], bv2 = B2[c2 * 8 + chunk];
        uint2 av3 = A2[r3 * 8 + chunk], bv3 = B2[c3 * 8 + chunk];
#pragma unroll
        for (int u = 0; u < 4; u++) {
            uint2 av = (u == 0) ? av0 : (u == 1) ? av1 : (u == 2) ? av2 : av3;
            uint2 bv = (u == 0) ? bv0 : (u == 1) ? bv1 : (u == 2) ? bv2 : bv3;
            float2 a0 = __half22float2(*(const __half2*)&av.x);
            float2 a1 = __half22float2(*(const __half2*)&av.y);
            float2 b0 = __half22float2(*(const __half2*)&bv.x);
            float2 b1 = __half22float2(*(const __half2*)&bv.y);
            float y;
            y = a0.x + b0.x; s[0] += y; q[0] = fmaf(y, y, q[0]);
            y = a0.y + b0.y; s[1] += y; q[1] = fmaf(y, y, q[1]);
            y = a1.x + b1.x; s[2] += y; q[2] = fmaf(y, y, q[2]);
            y = a1.y + b1.y; s[3] += y; q[3] = fmaf(y, y, q[3]);
        }
    }
#pragma unroll
    for (int off = 8; off < 32; off <<= 1) {
#pragma unroll
        for (int i = 0; i < 4; i++) {
            s[i] += __shfl_xor_sync(0xffffffffu, s[i], off);
            q[i] += __shfl_xor_sync(0xffffffffu, q[i], off);
        }
    }
    __shared__ float sh[64];
    if (threadIdx.x < 64) sh[threadIdx.x] = 0.f;
    __syncthreads();
    int lane = threadIdx.x & 31;
    if (lane < 8) {
#pragma unroll
        for (int i = 0; i < 4; i++) {
            atomicAdd(&sh[chunk * 4 + i], s[i]);
            atomicAdd(&sh[32 + chunk * 4 + i], q[i]);
        }
    }
    __syncthreads();
    if (threadIdx.x < 64) atomicAdd(&g_stat1[threadIdx.x], sh[threadIdx.x]);
}

// ---------------- K4: gather -> fp16 SMEM -> mt-tiled tensor GEMM ----------
#define HT 40  // fp16 h-tile stride (halves)
__global__ void __launch_bounds__(128, 6) k4_main(const int* __restrict__ ei,
                                                  const float* __restrict__ W2,
                                                  const float* __restrict__ b2,
                                                  const float* __restrict__ gamma1,
                                                  const float* __restrict__ beta1) {
    __shared__ __half sh_h[256 * HT];   // 20.5 KB
    __shared__ __half sWT[C * C];       // W2^T fp16 [n][k]
    __shared__ float sS1[C], sT1[C];
    __shared__ float sStat[4 * 64];
    int tid = threadIdx.x;

    for (int i = tid; i < C * C; i += 128) {
        int k = i >> 5, n = i & 31;
        sWT[n * C + k] = __float2half(W2[i]);
    }
    if (tid < C) {
        const float invE = 1.f / (float)N_EDGES;
        float mean = g_stat1[tid] * invE;
        float var = g_stat1[32 + tid] * invE - mean * mean;
        float s = gamma1[tid] * rsqrtf(var + BN_EPS);
        sS1[tid] = s;
        sT1[tid] = beta1[tid] - mean * s;
    }
    __syncthreads();

    // ---- phase 1: 8 lanes/edge fp16 gather + BN1 + ReLU -> fp16 tile ----
    int q = tid & 7;
    const uint2* A2 = (const uint2*)g_Ah;
    const uint2* B2 = (const uint2*)g_Bh;
    float s1v[4], t1v[4];
#pragma unroll
    for (int j = 0; j < 4; j++) { s1v[j] = sS1[q * 4 + j]; t1v[j] = sT1[q * 4 + j]; }
#pragma unroll
    for (int r = 0; r < 16; r++) {
        int el = (tid >> 3) + r * 16;
        int e = blockIdx.x * 256 + el;
        int row = ei[e];
        int col = ei[N_EDGES + e];
        uint2 av = A2[row * 8 + q];
        uint2 bv = B2[col * 8 + q];
        float2 a0 = __half22float2(*(const __half2*)&av.x);
        float2 a1 = __half22float2(*(const __half2*)&av.y);
        float2 b0 = __half22float2(*(const __half2*)&bv.x);
        float2 b1 = __half22float2(*(const __half2*)&bv.y);
        float h0 = fmaxf(fmaf(a0.x + b0.x, s1v[0], t1v[0]), 0.f);
        float h1 = fmaxf(fmaf(a0.y + b0.y, s1v[1], t1v[1]), 0.f);
        float h2 = fmaxf(fmaf(a1.x + b1.x, s1v[2], t1v[2]), 0.f);
        float h3 = fmaxf(fmaf(a1.y + b1.y, s1v[3], t1v[3]), 0.f);
        __half2 p01 = __floats2half2_rn(h0, h1);
        __half2 p23 = __floats2half2_rn(h2, h3);
        *(uint2*)(&sh_h[el * HT + q * 4]) = make_uint2(h2_bits(p01), h2_bits(p23));
    }
    __syncthreads();

    // ---- phase 2: mt-tiled GEMM (short-lived accumulators) ----
    int w = tid >> 5, l = tid & 31;
    int lq = l & 3, lr = l >> 2;

    unsigned bfr[4][2][2];
#pragma unroll
    for (int nt = 0; nt < 4; nt++)
#pragma unroll
        for (int kk = 0; kk < 2; kk++) {
            const __half* base = sWT + (lr + 8 * nt) * C + 2 * lq + 16 * kk;
            bfr[nt][kk][0] = *(const unsigned*)(base);
            bfr[nt][kk][1] = *(const unsigned*)(base + 8);
        }
    float bx[4], by[4];
#pragma unroll
    for (int nt = 0; nt < 4; nt++) {
        bx[nt] = b2[2 * lq + 8 * nt];
        by[nt] = b2[2 * lq + 8 * nt + 1];
    }
    float sv[4][2], qv[4][2];
#pragma unroll
    for (int nt = 0; nt < 4; nt++) { sv[nt][0] = sv[nt][1] = qv[nt][0] = qv[nt][1] = 0.f; }

    size_t ebase = (size_t)blockIdx.x * 256 + w * 64;
#pragma unroll
    for (int mt = 0; mt < 4; mt++) {
        float d[4][4];
#pragma unroll
        for (int nt = 0; nt < 4; nt++) {
            d[nt][0] = bx[nt]; d[nt][1] = by[nt];
            d[nt][2] = bx[nt]; d[nt][3] = by[nt];
        }
        int r0 = w * 64 + mt * 16 + lr;
#pragma unroll
        for (int kk = 0; kk < 2; kk++) {
            unsigned a0 = *(const unsigned*)(&sh_h[r0 * HT + 2 * lq + 16 * kk]);
            unsigned a1 = *(const unsigned*)(&sh_h[(r0 + 8) * HT + 2 * lq + 16 * kk]);
            unsigned a2 = *(const unsigned*)(&sh_h[r0 * HT + 2 * lq + 8 + 16 * kk]);
            unsigned a3 = *(const unsigned*)(&sh_h[(r0 + 8) * HT + 2 * lq + 8 + 16 * kk]);
#pragma unroll
            for (int nt = 0; nt < 4; nt++) {
                asm volatile(
                    "mma.sync.aligned.m16n8k16.row.col.f32.f16.f16.f32 "
                    "{%0,%1,%2,%3}, {%4,%5,%6,%7}, {%8,%9}, {%0,%1,%2,%3};"
                    : "+f"(d[nt][0]), "+f"(d[nt][1]), "+f"(d[nt][2]), "+f"(d[nt][3])
                    : "r"(a0), "r"(a1), "r"(a2), "r"(a3),
                      "r"(bfr[nt][kk][0]), "r"(bfr[nt][kk][1]));
            }
        }
        // store this mt-tile + stats
        size_t row0 = ebase + mt * 16 + lr;
        size_t row1 = row0 + 8;
#pragma unroll
        for (int nt = 0; nt < 4; nt++) {
            float d0 = d[nt][0], d1 = d[nt][1], d2 = d[nt][2], d3 = d[nt][3];
            __half2 ph0 = __floats2half2_rn(d0, d1);
            __half2 ph1 = __floats2half2_rn(d2, d3);
            int cw = 2 * lq + 8 * nt;
            *(unsigned*)(g_y2h + row0 * C + cw) = h2_bits(ph0);
            *(unsigned*)(g_y2h + row1 * C + cw) = h2_bits(ph1);
            sv[nt][0] += d0 + d2;  qv[nt][0] += d0 * d0 + d2 * d2;
            sv[nt][1] += d1 + d3;  qv[nt][1] += d1 * d1 + d3 * d3;
        }
    }

    // ---- stats2 block reduce ----
#pragma unroll
    for (int off = 4; off < 32; off <<= 1) {
#pragma unroll
        for (int nt = 0; nt < 4; nt++)
#pragma unroll
            for (int j = 0; j < 2; j++) {
                sv[nt][j] += __shfl_xor_sync(0xffffffffu, sv[nt][j], off);
                qv[nt][j] += __shfl_xor_sync(0xffffffffu, qv[nt][j], off);
            }
    }
    if (lr == 0) {
#pragma unroll
        for (int nt = 0; nt < 4; nt++)
#pragma unroll
            for (int j = 0; j < 2; j++) {
                int c = 2 * lq + 8 * nt + j;
                sStat[w * 64 + c] = sv[nt][j];
                sStat[w * 64 + 32 + c] = qv[nt][j];
            }
    }
    __syncthreads();
    if (tid < 64)
        atomicAdd(&g_stat2[tid],
                  sStat[tid] + sStat[64 + tid] + sStat[128 + tid] + sStat[192 + tid]);
}

// ---------------- K7: BN2+ReLU + vector atomic scatter ---------------------
__global__ void __launch_bounds__(256) k7_scatter(const int* __restrict__ ei,
                                                  const float* __restrict__ gamma2,
                                                  const float* __restrict__ beta2,
                                                  float* __restrict__ out) {
    __shared__ float sS2[C], sT2[C];
    if (threadIdx.x < C) {
        int c = threadIdx.x;
        const float invE = 1.f / (float)N_EDGES;
        float mean = g_stat2[c] * invE;
        float var = g_stat2[32 + c] * invE - mean * mean;
        float s = gamma2[c] * rsqrtf(var + BN_EPS);
        sS2[c] = s;
        sT2[c] = beta2[c] - mean * s;
    }
    __syncthreads();
    int g = blockIdx.x * blockDim.x + threadIdx.x; // grid = E*4/256
    int e = g >> 2;
    int chunk = g & 3; // 8 channels
    int row = ei[e];
    const uint4* Y = (const uint4*)g_y2h;
    uint4 v = Y[(size_t)e * 4 + chunk];
    const unsigned* w = (const unsigned*)&v;
    float h[8];
#pragma unroll
    for (int p = 0; p < 4; p++) {
        float2 f = __half22float2(*(const __half2*)&w[p]);
        int c = chunk * 8 + 2 * p;
        h[2 * p]     = fmaxf(fmaf(f.x, sS2[c],     sT2[c]),     0.f);
        h[2 * p + 1] = fmaxf(fmaf(f.y, sS2[c + 1], sT2[c + 1]), 0.f);
    }
    float* dst = out + row * C + chunk * 8;
    red_add_v4(dst,     h[0], h[1], h[2], h[3]);
    red_add_v4(dst + 4, h[4], h[5], h[6], h[7]);
}

// ---------------- launch ----------------------------------------------------
extern "C" void kernel_launch(void* const* d_in, const int* in_sizes, int n_in,
                              void* d_out, int out_size) {
    const float* x      = (const float*)d_in[0];
    const float* W1     = (const float*)d_in[1];
    const float* b1     = (const float*)d_in[2];
    const float* gamma1 = (const float*)d_in[3];
    const float* beta1  = (const float*)d_in[4];
    const float* W2     = (const float*)d_in[5];
    const float* b2     = (const float*)d_in[6];
    const float* gamma2 = (const float*)d_in[7];
    const float* beta2  = (const float*)d_in[8];
    const int* ei       = (const int*)d_in[9];
    float* out = (float*)d_out;

    k1_node<<<N_NODES / 8, 256>>>(x, W1, b1, out);
    k2_stats1<<<2048, 256>>>(ei);
    k4_main<<<N_EDGES / 256, 128>>>(ei, W2, b2, gamma1, beta1);
    k7_scatter<<<N_EDGES * 4 / 256, 256>>>(ei, gamma2, beta2, out);
}